// round 9
// baseline (speedup 1.0000x reference)
#include <cuda_runtime.h>
#include <cuda_bf16.h>
#include <math.h>
#include <stdint.h>

#define BB 8
#define LL 2048
#define DD 1024
#define HH 1024

// ---------------------------------------------------------------------------
// Scratch (bf16 split pairs + fp32 scores)
// ---------------------------------------------------------------------------
__device__ __nv_bfloat16 g_iq_h[BB * LL * DD], g_iq_l[BB * LL * DD];
__device__ __nv_bfloat16 g_ik_h[BB * LL * DD], g_ik_l[BB * LL * DD];
__device__ __nv_bfloat16 g_Wqt_h[HH * DD], g_Wqt_l[HH * DD];
__device__ __nv_bfloat16 g_Wkt_h[HH * DD], g_Wkt_l[HH * DD];
__device__ __nv_bfloat16 g_Q_h[BB * LL * HH], g_Q_l[BB * LL * HH];
__device__ __nv_bfloat16 g_K_h[BB * LL * HH], g_K_l[BB * LL * HH];
__device__ __nv_bfloat16 g_Vt_h[BB * DD * LL], g_Vt_l[BB * DD * LL];
__device__ __nv_bfloat16 g_P_h[(size_t)BB * LL * LL], g_P_l[(size_t)BB * LL * LL];
__device__ float g_S[(size_t)BB * LL * LL];

// ---------------------------------------------------------------------------
__device__ __forceinline__ uint32_t smem_u32(const void* p) {
    uint32_t a;
    asm("{ .reg .u64 t; cvta.to.shared.u64 t, %1; cvt.u32.u64 %0, t; }" : "=r"(a) : "l"(p));
    return a;
}

#define CP_ASYNC16(dst, src) \
    asm volatile("cp.async.cg.shared.global [%0], [%1], 16;" :: "r"(dst), "l"(src))
#define CP_COMMIT() asm volatile("cp.async.commit_group;" ::: "memory")
#define CP_WAIT(n)  asm volatile("cp.async.wait_group %0;" :: "n"(n) : "memory")

#define LDSM4(R, addr) \
    asm volatile("ldmatrix.sync.aligned.m8n8.x4.shared.b16 {%0,%1,%2,%3}, [%4];" \
        : "=r"((R)[0]), "=r"((R)[1]), "=r"((R)[2]), "=r"((R)[3]) : "r"(addr))

#define MMA16816(D, A, B0, B1) \
    asm volatile("mma.sync.aligned.m16n8k16.row.col.f32.bf16.bf16.f32 " \
        "{%0,%1,%2,%3},{%4,%5,%6,%7},{%8,%9},{%0,%1,%2,%3};" \
        : "+f"((D)[0]), "+f"((D)[1]), "+f"((D)[2]), "+f"((D)[3]) \
        : "r"((A)[0]), "r"((A)[1]), "r"((A)[2]), "r"((A)[3]), "r"(B0), "r"(B1))

__device__ __forceinline__ void split_val(float x, __nv_bfloat16& h, __nv_bfloat16& l) {
    h = __float2bfloat16(x);
    l = __float2bfloat16(x - __bfloat162float(h));
}

// ---------------------------------------------------------------------------
// bf16x3 NT GEMM: C[m,n] = alpha * sum_k A[m,k]*B[n,k] (+bias[n])
// CTA tile 256x128, BK=32, 3-stage cp.async pipeline, 8 warps (4m x 2n),
// warp tile 64x64 (MMA:LDSM = 6:1). Passes ordered hh -> lh -> (load bl) hl
// so bh/al registers recycle into bl.
// Smem stage layout: Ah(20480) Al(20480) Bh(10240) Bl(10240) = 61440.
// ---------------------------------------------------------------------------
#define A_T      20480          // 256 rows * 80B
#define B_T      10240          // 128 rows * 80B
#define STAGE_SZ 61440
template <bool ADD_BIAS, bool SPLIT_OUT>
__global__ __launch_bounds__(256, 1) void gemm_bf16x3(
    const __nv_bfloat16* __restrict__ Ah, const __nv_bfloat16* __restrict__ Al,
    const __nv_bfloat16* __restrict__ Bh, const __nv_bfloat16* __restrict__ Bl,
    const float* __restrict__ bias,
    float* __restrict__ Cf, __nv_bfloat16* __restrict__ Ch, __nv_bfloat16* __restrict__ Cl,
    int M, int N, int K, float alpha, size_t sA, size_t sB, size_t sC)
{
    extern __shared__ char smem[];
    const uint32_t sbase = smem_u32(smem);

    Ah += (size_t)blockIdx.z * sA;  Al += (size_t)blockIdx.z * sA;
    Bh += (size_t)blockIdx.z * sB;  Bl += (size_t)blockIdx.z * sB;
    if (SPLIT_OUT) { Ch += (size_t)blockIdx.z * sC; Cl += (size_t)blockIdx.z * sC; }
    else           { Cf += (size_t)blockIdx.z * sC; }

    const int t    = threadIdx.x;
    const int lane = t & 31;
    const int wid  = t >> 5;
    const int wm   = wid >> 1;         // 4 warps along M (64 rows each)
    const int wn   = wid & 1;          // 2 warps along N (64 cols each)
    const int rowBase = blockIdx.y * 256;
    const int colBase = blockIdx.x * 128;

    const int nIter = K >> 5;

    // ldmatrix fragment offsets (stage-relative; +32B per ks)
    uint32_t aoff[4], boff[4];
#pragma unroll
    for (int mt = 0; mt < 4; mt++) {
        uint32_t r = wm * 64 + mt * 16 + (lane & 7) + ((lane >> 3) & 1) * 8;
        uint32_t c = ((lane >> 4) & 1) * 8;
        aoff[mt] = r * 80 + c * 2;
    }
#pragma unroll
    for (int np = 0; np < 4; np++) {
        uint32_t r = wn * 64 + np * 16 + (lane & 7) + ((lane >> 4) & 1) * 8;
        uint32_t c = ((lane >> 3) & 1) * 8;
        boff[np] = 2 * A_T + r * 80 + c * 2;
    }

    // Producer offsets: thread t -> row base t>>2, 16B segment t&3
    const int pr   = t >> 2;
    const uint32_t psof = (uint32_t)(pr * 80 + (t & 3) * 16);
    const int pk   = (t & 3) * 8;

    auto produce = [&](int kt, int stage) {
        const uint32_t s0 = sbase + stage * STAGE_SZ;
        const int k0 = kt << 5;
#pragma unroll
        for (int i = 0; i < 4; i++) {              // A: 256 rows
            int r = pr + i * 64;
            uint32_t sof = psof + (uint32_t)i * (64 * 80);
            size_t gof = (size_t)(rowBase + r) * K + k0 + pk;
            CP_ASYNC16(s0 + sof,        Ah + gof);
            CP_ASYNC16(s0 + A_T + sof,  Al + gof);
        }
#pragma unroll
        for (int i = 0; i < 2; i++) {              // B: 128 rows
            int r = pr + i * 64;
            uint32_t sof = psof + (uint32_t)i * (64 * 80);
            size_t gob = (size_t)(colBase + r) * K + k0 + pk;
            CP_ASYNC16(s0 + 2 * A_T + sof,        Bh + gob);
            CP_ASYNC16(s0 + 2 * A_T + B_T + sof,  Bl + gob);
        }
        CP_COMMIT();
    };

    float acc[4][8][4];
#pragma unroll
    for (int i = 0; i < 4; i++)
#pragma unroll
        for (int j = 0; j < 8; j++)
#pragma unroll
            for (int v = 0; v < 4; v++) acc[i][j][v] = 0.0f;

    produce(0, 0);
    produce(1, 1);

    int stage = 0;
    for (int kt = 0; kt < nIter; kt++) {
        if (kt == nIter - 1) { CP_WAIT(0); } else { CP_WAIT(1); }
        __syncthreads();
        if (kt + 2 < nIter) {
            int ps = stage + 2; if (ps >= 3) ps -= 3;
            produce(kt + 2, ps);
        }

        const uint32_t s0 = sbase + stage * STAGE_SZ;

#pragma unroll
        for (int ks = 0; ks < 2; ks++) {
            const uint32_t kof = ks * 32;
            {
                uint32_t ah[4][4], al[4][4], bh[8][2];
#pragma unroll
                for (int mt = 0; mt < 4; mt++) {
                    uint32_t ad = s0 + aoff[mt] + kof;
                    LDSM4(ah[mt], ad);
                    LDSM4(al[mt], ad + A_T);
                }
#pragma unroll
                for (int np = 0; np < 4; np++)
                    LDSM4(&bh[2 * np][0], s0 + boff[np] + kof);
                // Pass 1: hi*hi
#pragma unroll
                for (int mt = 0; mt < 4; mt++)
#pragma unroll
                    for (int nt = 0; nt < 8; nt++)
                        MMA16816(acc[mt][nt], ah[mt], bh[nt][0], bh[nt][1]);
                // Pass 2: lo*hi  (al dies after this; bh dies after this)
#pragma unroll
                for (int mt = 0; mt < 4; mt++)
#pragma unroll
                    for (int nt = 0; nt < 8; nt++)
                        MMA16816(acc[mt][nt], al[mt], bh[nt][0], bh[nt][1]);
                // Pass 3: hi*lo  (bl reuses dead bh/al registers)
                uint32_t bl[8][2];
#pragma unroll
                for (int np = 0; np < 4; np++)
                    LDSM4(&bl[2 * np][0], s0 + boff[np] + B_T + kof);
#pragma unroll
                for (int mt = 0; mt < 4; mt++)
#pragma unroll
                    for (int nt = 0; nt < 8; nt++)
                        MMA16816(acc[mt][nt], ah[mt], bl[nt][0], bl[nt][1]);
            }
        }
        stage++; if (stage >= 3) stage = 0;
    }

    // Epilogue
#pragma unroll
    for (int mt = 0; mt < 4; mt++) {
#pragma unroll
        for (int nt = 0; nt < 8; nt++) {
            int row = rowBase + wm * 64 + mt * 16 + (lane >> 2);
            int col = colBase + wn * 64 + nt * 8 + 2 * (lane & 3);
            float v0 = acc[mt][nt][0] * alpha;
            float v1 = acc[mt][nt][1] * alpha;
            float v2 = acc[mt][nt][2] * alpha;
            float v3 = acc[mt][nt][3] * alpha;
            if (ADD_BIAS) {
                float b0 = bias[col], b1 = bias[col + 1];
                v0 += b0; v1 += b1; v2 += b0; v3 += b1;
            }
            if (SPLIT_OUT) {
                __nv_bfloat162 h01, l01, h23, l23;
                split_val(v0, h01.x, l01.x); split_val(v1, h01.y, l01.y);
                split_val(v2, h23.x, l23.x); split_val(v3, h23.y, l23.y);
                *(__nv_bfloat162*)(Ch + (size_t)row * N + col)       = h01;
                *(__nv_bfloat162*)(Cl + (size_t)row * N + col)       = l01;
                *(__nv_bfloat162*)(Ch + (size_t)(row + 8) * N + col) = h23;
                *(__nv_bfloat162*)(Cl + (size_t)(row + 8) * N + col) = l23;
            } else {
                *(float2*)(Cf + (size_t)row * N + col)       = make_float2(v0, v1);
                *(float2*)(Cf + (size_t)(row + 8) * N + col) = make_float2(v2, v3);
            }
        }
    }
}

// ---------------------------------------------------------------------------
// Elementwise fp32 -> (hi, lo) bf16 split. 4 elements / thread.
// ---------------------------------------------------------------------------
__global__ __launch_bounds__(256) void split_f32(
    const float* __restrict__ in, __nv_bfloat16* __restrict__ h,
    __nv_bfloat16* __restrict__ l)
{
    size_t i = ((size_t)blockIdx.x * 256 + threadIdx.x) * 4;
    float4 v = *(const float4*)(in + i);
    __nv_bfloat162 h01, l01, h23, l23;
    split_val(v.x, h01.x, l01.x); split_val(v.y, h01.y, l01.y);
    split_val(v.z, h23.x, l23.x); split_val(v.w, h23.y, l23.y);
    *(__nv_bfloat162*)(h + i)     = h01;
    *(__nv_bfloat162*)(l + i)     = l01;
    *(__nv_bfloat162*)(h + i + 2) = h23;
    *(__nv_bfloat162*)(l + i + 2) = l23;
}

// ---------------------------------------------------------------------------
// Transpose + split: out_{h,l}[c][r] = split(in[r][c]); batched over z.
// ---------------------------------------------------------------------------
__global__ __launch_bounds__(256) void transpose_split(
    const float* __restrict__ in, __nv_bfloat16* __restrict__ oh,
    __nv_bfloat16* __restrict__ ol, int R, int C)
{
    __shared__ float tile[32][33];
    in += (size_t)blockIdx.z * R * C;
    oh += (size_t)blockIdx.z * R * C;
    ol += (size_t)blockIdx.z * R * C;
    const int r0 = blockIdx.y * 32, c0 = blockIdx.x * 32;
    const int tx = threadIdx.x, ty = threadIdx.y;
#pragma unroll
    for (int i = ty; i < 32; i += 8)
        tile[i][tx] = in[(size_t)(r0 + i) * C + c0 + tx];
    __syncthreads();
#pragma unroll
    for (int i = ty; i < 32; i += 8) {
        float x = tile[tx][i];
        __nv_bfloat16 h, l;
        split_val(x, h, l);
        size_t o = (size_t)(c0 + i) * R + r0 + tx;
        oh[o] = h;
        ol[o] = l;
    }
}

// ---------------------------------------------------------------------------
// Fused mask + softmax; reads fp32 S, writes split bf16 P.
// ---------------------------------------------------------------------------
__global__ __launch_bounds__(256) void softmax_mask(
    const float* __restrict__ S, const float* __restrict__ mask,
    __nv_bfloat16* __restrict__ Ph, __nv_bfloat16* __restrict__ Pl)
{
    const int row = blockIdx.x;
    const int b   = row >> 11;
    const int q   = row & (LL - 1);
    const float* mrow = mask + (size_t)b * LL;
    const float mq = (mrow[q] > 0.5f) ? 0.0f : -1.0e9f;
    const float* srow = S + (size_t)row * LL;

    const int t = threadIdx.x;
    float vals[8];
    float lmax = -INFINITY;

#pragma unroll
    for (int v = 0; v < 2; v++) {
        int idx = v * 1024 + t * 4;
        float4 f  = *(const float4*)(srow + idx);
        float4 mk = *(const float4*)(mrow + idx);
        float a;
        a = ((mk.x > 0.5f) ? 0.0f : -1.0e9f) * mq; vals[v * 4 + 0] = f.x + a;
        a = ((mk.y > 0.5f) ? 0.0f : -1.0e9f) * mq; vals[v * 4 + 1] = f.y + a;
        a = ((mk.z > 0.5f) ? 0.0f : -1.0e9f) * mq; vals[v * 4 + 2] = f.z + a;
        a = ((mk.w > 0.5f) ? 0.0f : -1.0e9f) * mq; vals[v * 4 + 3] = f.w + a;
#pragma unroll
        for (int j = 0; j < 4; j++) lmax = fmaxf(lmax, vals[v * 4 + j]);
    }

    __shared__ float red[256];
    red[t] = lmax;
    __syncthreads();
#pragma unroll
    for (int s = 128; s > 0; s >>= 1) {
        if (t < s) red[t] = fmaxf(red[t], red[t + s]);
        __syncthreads();
    }
    const float rmax = red[0];
    __syncthreads();

    float lsum = 0.0f;
#pragma unroll
    for (int i = 0; i < 8; i++) {
        vals[i] = expf(vals[i] - rmax);
        lsum += vals[i];
    }
    red[t] = lsum;
    __syncthreads();
#pragma unroll
    for (int s = 128; s > 0; s >>= 1) {
        if (t < s) red[t] += red[t + s];
        __syncthreads();
    }
    const float inv = 1.0f / red[0];

#pragma unroll
    for (int v = 0; v < 2; v++) {
        int idx = v * 1024 + t * 4;
        float p0 = vals[v * 4 + 0] * inv, p1 = vals[v * 4 + 1] * inv;
        float p2 = vals[v * 4 + 2] * inv, p3 = vals[v * 4 + 3] * inv;
        __nv_bfloat162 h01, l01, h23, l23;
        split_val(p0, h01.x, l01.x); split_val(p1, h01.y, l01.y);
        split_val(p2, h23.x, l23.x); split_val(p3, h23.y, l23.y);
        size_t o = (size_t)row * LL + idx;
        *(__nv_bfloat162*)(Ph + o)     = h01;
        *(__nv_bfloat162*)(Pl + o)     = l01;
        *(__nv_bfloat162*)(Ph + o + 2) = h23;
        *(__nv_bfloat162*)(Pl + o + 2) = l23;
    }
}

// ---------------------------------------------------------------------------
extern "C" void kernel_launch(void* const* d_in, const int* in_sizes, int n_in,
                              void* d_out, int out_size)
{
    const float* in_q  = (const float*)d_in[0];
    const float* in_k  = (const float*)d_in[1];
    const float* kmask = (const float*)d_in[2];
    const float* Wq    = (const float*)d_in[3];
    const float* bq    = (const float*)d_in[4];
    const float* Wk    = (const float*)d_in[5];
    const float* bk    = (const float*)d_in[6];
    float* out = (float*)d_out;

    __nv_bfloat16 *iqh, *iql, *ikh, *ikl, *wqh, *wql, *wkh, *wkl;
    __nv_bfloat16 *Qh, *Ql, *Kh, *Kl, *Vh, *Vl, *Ph, *Pl;
    float* Sp;
    cudaGetSymbolAddress((void**)&iqh, g_iq_h);  cudaGetSymbolAddress((void**)&iql, g_iq_l);
    cudaGetSymbolAddress((void**)&ikh, g_ik_h);  cudaGetSymbolAddress((void**)&ikl, g_ik_l);
    cudaGetSymbolAddress((void**)&wqh, g_Wqt_h); cudaGetSymbolAddress((void**)&wql, g_Wqt_l);
    cudaGetSymbolAddress((void**)&wkh, g_Wkt_h); cudaGetSymbolAddress((void**)&wkl, g_Wkt_l);
    cudaGetSymbolAddress((void**)&Qh,  g_Q_h);   cudaGetSymbolAddress((void**)&Ql,  g_Q_l);
    cudaGetSymbolAddress((void**)&Kh,  g_K_h);   cudaGetSymbolAddress((void**)&Kl,  g_K_l);
    cudaGetSymbolAddress((void**)&Vh,  g_Vt_h);  cudaGetSymbolAddress((void**)&Vl,  g_Vt_l);
    cudaGetSymbolAddress((void**)&Ph,  g_P_h);   cudaGetSymbolAddress((void**)&Pl,  g_P_l);
    cudaGetSymbolAddress((void**)&Sp,  g_S);

    const int SMEM_BYTES = 3 * STAGE_SZ;   // 184320
    cudaFuncSetAttribute(gemm_bf16x3<true, true>,
                         cudaFuncAttributeMaxDynamicSharedMemorySize, SMEM_BYTES);
    cudaFuncSetAttribute(gemm_bf16x3<false, false>,
                         cudaFuncAttributeMaxDynamicSharedMemorySize, SMEM_BYTES);

    // 0) Splits + transposed splits
    split_f32<<<BB * LL * DD / 1024, 256>>>(in_q, iqh, iql);
    split_f32<<<BB * LL * DD / 1024, 256>>>(in_k, ikh, ikl);
    {
        dim3 blk(32, 8);
        transpose_split<<<dim3(HH / 32, DD / 32, 1), blk>>>(Wq, wqh, wql, DD, HH);
        transpose_split<<<dim3(HH / 32, DD / 32, 1), blk>>>(Wk, wkh, wkl, DD, HH);
        transpose_split<<<dim3(DD / 32, LL / 32, BB), blk>>>(in_k, Vh, Vl, LL, DD);
    }

    // 1) Projections (NT, split output)
    {
        dim3 grid(HH / 128, (BB * LL) / 256, 1);
        gemm_bf16x3<true, true><<<grid, 256, SMEM_BYTES>>>(
            iqh, iql, wqh, wql, bq, nullptr, Qh, Ql,
            BB * LL, HH, DD, 1.0f, 0, 0, 0);
        gemm_bf16x3<true, true><<<grid, 256, SMEM_BYTES>>>(
            ikh, ikl, wkh, wkl, bk, nullptr, Kh, Kl,
            BB * LL, HH, DD, 1.0f, 0, 0, 0);
    }

    // 2) Scores: S[b] = (Q[b] @ K[b]^T) / 32
    {
        dim3 grid(LL / 128, LL / 256, BB);
        gemm_bf16x3<false, false><<<grid, 256, SMEM_BYTES>>>(
            Qh, Ql, Kh, Kl, nullptr, Sp, nullptr, nullptr,
            LL, LL, HH, 0.03125f,
            (size_t)LL * HH, (size_t)LL * HH, (size_t)LL * LL);
    }

    // 3) Masked softmax -> split P
    softmax_mask<<<BB * LL, 256>>>(Sp, kmask, Ph, Pl);

    // 4) Output: out[b] = P[b] @ in_k[b]  (NT with Vt)
    {
        dim3 grid(DD / 128, LL / 256, BB);
        gemm_bf16x3<false, false><<<grid, 256, SMEM_BYTES>>>(
            Ph, Pl, Vh, Vl, nullptr, out, nullptr, nullptr,
            LL, DD, LL, 1.0f,
            (size_t)LL * LL, (size_t)DD * LL, (size_t)LL * DD);
    }
}

// round 11
// speedup vs baseline: 1.2530x; 1.2530x over previous
#include <cuda_runtime.h>
#include <cuda_bf16.h>
#include <math.h>
#include <stdint.h>

#define BB 8
#define LL 2048
#define DD 1024
#define HH 1024

// ---------------------------------------------------------------------------
// Scratch (bf16 split pairs + fp32 scores)
// ---------------------------------------------------------------------------
__device__ __nv_bfloat16 g_iq_h[BB * LL * DD], g_iq_l[BB * LL * DD];
__device__ __nv_bfloat16 g_ik_h[BB * LL * DD], g_ik_l[BB * LL * DD];
__device__ __nv_bfloat16 g_Wqt_h[HH * DD], g_Wqt_l[HH * DD];
__device__ __nv_bfloat16 g_Wkt_h[HH * DD], g_Wkt_l[HH * DD];
__device__ __nv_bfloat16 g_Q_h[BB * LL * HH], g_Q_l[BB * LL * HH];
__device__ __nv_bfloat16 g_K_h[BB * LL * HH], g_K_l[BB * LL * HH];
__device__ __nv_bfloat16 g_Vt_h[BB * DD * LL], g_Vt_l[BB * DD * LL];
__device__ __nv_bfloat16 g_P_h[(size_t)BB * LL * LL], g_P_l[(size_t)BB * LL * LL];
__device__ float g_S[(size_t)BB * LL * LL];

// ---------------------------------------------------------------------------
__device__ __forceinline__ uint32_t smem_u32(const void* p) {
    uint32_t a;
    asm("{ .reg .u64 t; cvta.to.shared.u64 t, %1; cvt.u32.u64 %0, t; }" : "=r"(a) : "l"(p));
    return a;
}

#define CP_ASYNC16(dst, src) \
    asm volatile("cp.async.cg.shared.global [%0], [%1], 16;" :: "r"(dst), "l"(src))
#define CP_COMMIT() asm volatile("cp.async.commit_group;" ::: "memory")
#define CP_WAIT(n)  asm volatile("cp.async.wait_group %0;" :: "n"(n) : "memory")

#define LDSM4(R, addr) \
    asm volatile("ldmatrix.sync.aligned.m8n8.x4.shared.b16 {%0,%1,%2,%3}, [%4];" \
        : "=r"((R)[0]), "=r"((R)[1]), "=r"((R)[2]), "=r"((R)[3]) : "r"(addr))

#define MMA16816(D, A, B0, B1) \
    asm volatile("mma.sync.aligned.m16n8k16.row.col.f32.bf16.bf16.f32 " \
        "{%0,%1,%2,%3},{%4,%5,%6,%7},{%8,%9},{%0,%1,%2,%3};" \
        : "+f"((D)[0]), "+f"((D)[1]), "+f"((D)[2]), "+f"((D)[3]) \
        : "r"((A)[0]), "r"((A)[1]), "r"((A)[2]), "r"((A)[3]), "r"(B0), "r"(B1))

__device__ __forceinline__ void split_val(float x, __nv_bfloat16& h, __nv_bfloat16& l) {
    h = __float2bfloat16(x);
    l = __float2bfloat16(x - __bfloat162float(h));
}

// ---------------------------------------------------------------------------
// bf16x3 NT GEMM: C[m,n] = alpha * sum_k A[m,k]*B[n,k] (+bias[n])
// CTA 128x128, BK=32, 3-stage cp.async pipeline (one sync per chunk),
// 8 warps (4m x 2n), warp tile 32x64, XOR-swizzled 64B-stride smem (no pad).
// Swizzle: 16B chunk c of row r stored at chunk (c ^ ((r>>1)&3)).
// Pass order hh -> lh -> (load bl) -> hl keeps bh/bl non-co-live.
// Stage layout: Ah@0 Al@8192 Bh@16384 Bl@24576, STAGE_SZ=32768.
// ---------------------------------------------------------------------------
#define STAGE_SZ 32768
template <bool ADD_BIAS, bool SPLIT_OUT>
__global__ __launch_bounds__(256, 2) void gemm_bf16x3(
    const __nv_bfloat16* __restrict__ Ah, const __nv_bfloat16* __restrict__ Al,
    const __nv_bfloat16* __restrict__ Bh, const __nv_bfloat16* __restrict__ Bl,
    const float* __restrict__ bias,
    float* __restrict__ Cf, __nv_bfloat16* __restrict__ Ch, __nv_bfloat16* __restrict__ Cl,
    int M, int N, int K, float alpha, size_t sA, size_t sB, size_t sC)
{
    extern __shared__ char smem[];
    const uint32_t sbase = smem_u32(smem);

    Ah += (size_t)blockIdx.z * sA;  Al += (size_t)blockIdx.z * sA;
    Bh += (size_t)blockIdx.z * sB;  Bl += (size_t)blockIdx.z * sB;
    if (SPLIT_OUT) { Ch += (size_t)blockIdx.z * sC; Cl += (size_t)blockIdx.z * sC; }
    else           { Cf += (size_t)blockIdx.z * sC; }

    const int t    = threadIdx.x;
    const int lane = t & 31;
    const int wid  = t >> 5;
    const int wm   = wid & 3;          // 4 warps along M (32 rows each)
    const int wn   = wid >> 2;         // 2 warps along N (64 cols each)
    const int rowBase = blockIdx.y * 128;
    const int colBase = blockIdx.x * 128;

    const int nIter = K >> 5;

    // ldmatrix fragment row bases + swizzle selectors
    uint32_t aRow[2], aSw[2], bRow[4], bSw[4];
    const uint32_t cbA = (lane >> 4) & 1;   // A chunk low bit
    const uint32_t cbB = (lane >> 3) & 1;   // B chunk low bit
#pragma unroll
    for (int mt = 0; mt < 2; mt++) {
        uint32_t r = wm * 32 + mt * 16 + (lane & 7) + ((lane >> 3) & 1) * 8;
        aRow[mt] = r * 64;
        aSw[mt]  = (r >> 1) & 3;
    }
#pragma unroll
    for (int np = 0; np < 4; np++) {
        uint32_t r = wn * 64 + np * 16 + (lane & 7) + ((lane >> 4) & 1) * 8;
        bRow[np] = r * 64;
        bSw[np]  = (r >> 1) & 3;
    }

    // Producer: thread t -> rows t>>2 and t>>2 + 64, chunk t&3 (16B each)
    const int pc = t & 3;

    auto produce = [&](int kt, int stg) {
        const uint32_t s0 = sbase + (uint32_t)stg * STAGE_SZ;
        const int k0 = kt << 5;
#pragma unroll
        for (int i = 0; i < 2; i++) {
            int r = (t >> 2) + i * 64;
            uint32_t sof = (uint32_t)(r * 64 + ((pc ^ ((r >> 1) & 3)) * 16));
            size_t ga = (size_t)(rowBase + r) * K + k0 + pc * 8;
            size_t gb = (size_t)(colBase + r) * K + k0 + pc * 8;
            CP_ASYNC16(s0 + sof,         Ah + ga);
            CP_ASYNC16(s0 + 8192 + sof,  Al + ga);
            CP_ASYNC16(s0 + 16384 + sof, Bh + gb);
            CP_ASYNC16(s0 + 24576 + sof, Bl + gb);
        }
        CP_COMMIT();
    };

    float acc[2][8][4];
#pragma unroll
    for (int i = 0; i < 2; i++)
#pragma unroll
        for (int j = 0; j < 8; j++)
#pragma unroll
            for (int v = 0; v < 4; v++) acc[i][j][v] = 0.0f;

    produce(0, 0);
    produce(1, 1);

    int stage = 0;
    for (int kt = 0; kt < nIter; kt++) {
        if (kt + 1 < nIter) { CP_WAIT(1); } else { CP_WAIT(0); }
        __syncthreads();                 // also guards stage reuse for produce below
        if (kt + 2 < nIter) {
            int ps = stage + 2; if (ps >= 3) ps -= 3;
            produce(kt + 2, ps);
        }

        const uint32_t s0 = sbase + (uint32_t)stage * STAGE_SZ;

#pragma unroll
        for (int ks = 0; ks < 2; ks++) {
            const uint32_t chA = ks * 2 + cbA;
            const uint32_t chB = ks * 2 + cbB;
            uint32_t ah[2][4], al[2][4], bh[8][2];
#pragma unroll
            for (int mt = 0; mt < 2; mt++) {
                uint32_t ad = s0 + aRow[mt] + ((chA ^ aSw[mt]) << 4);
                LDSM4(ah[mt], ad);
                LDSM4(al[mt], ad + 8192);
            }
#pragma unroll
            for (int np = 0; np < 4; np++) {
                uint32_t bd = s0 + 16384 + bRow[np] + ((chB ^ bSw[np]) << 4);
                LDSM4(&bh[2 * np][0], bd);
            }
            // Pass 1: hi*hi
#pragma unroll
            for (int mt = 0; mt < 2; mt++)
#pragma unroll
                for (int nt = 0; nt < 8; nt++)
                    MMA16816(acc[mt][nt], ah[mt], bh[nt][0], bh[nt][1]);
            // Pass 2: lo*hi (al, bh die after this)
#pragma unroll
            for (int mt = 0; mt < 2; mt++)
#pragma unroll
                for (int nt = 0; nt < 8; nt++)
                    MMA16816(acc[mt][nt], al[mt], bh[nt][0], bh[nt][1]);
            // Pass 3: hi*lo (bl reuses dead registers)
            uint32_t bl[8][2];
#pragma unroll
            for (int np = 0; np < 4; np++) {
                uint32_t bd = s0 + 24576 + bRow[np] + ((chB ^ bSw[np]) << 4);
                LDSM4(&bl[2 * np][0], bd);
            }
#pragma unroll
            for (int mt = 0; mt < 2; mt++)
#pragma unroll
                for (int nt = 0; nt < 8; nt++)
                    MMA16816(acc[mt][nt], ah[mt], bl[nt][0], bl[nt][1]);
        }
        stage++; if (stage >= 3) stage = 0;
    }

    // Epilogue
#pragma unroll
    for (int mt = 0; mt < 2; mt++) {
#pragma unroll
        for (int nt = 0; nt < 8; nt++) {
            int row = rowBase + wm * 32 + mt * 16 + (lane >> 2);
            int col = colBase + wn * 64 + nt * 8 + 2 * (lane & 3);
            float v0 = acc[mt][nt][0] * alpha;
            float v1 = acc[mt][nt][1] * alpha;
            float v2 = acc[mt][nt][2] * alpha;
            float v3 = acc[mt][nt][3] * alpha;
            if (ADD_BIAS) {
                float b0 = bias[col], b1 = bias[col + 1];
                v0 += b0; v1 += b1; v2 += b0; v3 += b1;
            }
            if (SPLIT_OUT) {
                __nv_bfloat162 h01, l01, h23, l23;
                split_val(v0, h01.x, l01.x); split_val(v1, h01.y, l01.y);
                split_val(v2, h23.x, l23.x); split_val(v3, h23.y, l23.y);
                *(__nv_bfloat162*)(Ch + (size_t)row * N + col)       = h01;
                *(__nv_bfloat162*)(Cl + (size_t)row * N + col)       = l01;
                *(__nv_bfloat162*)(Ch + (size_t)(row + 8) * N + col) = h23;
                *(__nv_bfloat162*)(Cl + (size_t)(row + 8) * N + col) = l23;
            } else {
                *(float2*)(Cf + (size_t)row * N + col)       = make_float2(v0, v1);
                *(float2*)(Cf + (size_t)(row + 8) * N + col) = make_float2(v2, v3);
            }
        }
    }
}

// ---------------------------------------------------------------------------
// Elementwise fp32 -> (hi, lo) bf16 split. 4 elements / thread.
// ---------------------------------------------------------------------------
__global__ __launch_bounds__(256) void split_f32(
    const float* __restrict__ in, __nv_bfloat16* __restrict__ h,
    __nv_bfloat16* __restrict__ l)
{
    size_t i = ((size_t)blockIdx.x * 256 + threadIdx.x) * 4;
    float4 v = *(const float4*)(in + i);
    __nv_bfloat162 h01, l01, h23, l23;
    split_val(v.x, h01.x, l01.x); split_val(v.y, h01.y, l01.y);
    split_val(v.z, h23.x, l23.x); split_val(v.w, h23.y, l23.y);
    *(__nv_bfloat162*)(h + i)     = h01;
    *(__nv_bfloat162*)(l + i)     = l01;
    *(__nv_bfloat162*)(h + i + 2) = h23;
    *(__nv_bfloat162*)(l + i + 2) = l23;
}

// ---------------------------------------------------------------------------
// Transpose + split: out_{h,l}[c][r] = split(in[r][c]); batched over z.
// ---------------------------------------------------------------------------
__global__ __launch_bounds__(256) void transpose_split(
    const float* __restrict__ in, __nv_bfloat16* __restrict__ oh,
    __nv_bfloat16* __restrict__ ol, int R, int C)
{
    __shared__ float tile[32][33];
    in += (size_t)blockIdx.z * R * C;
    oh += (size_t)blockIdx.z * R * C;
    ol += (size_t)blockIdx.z * R * C;
    const int r0 = blockIdx.y * 32, c0 = blockIdx.x * 32;
    const int tx = threadIdx.x, ty = threadIdx.y;
#pragma unroll
    for (int i = ty; i < 32; i += 8)
        tile[i][tx] = in[(size_t)(r0 + i) * C + c0 + tx];
    __syncthreads();
#pragma unroll
    for (int i = ty; i < 32; i += 8) {
        float x = tile[tx][i];
        __nv_bfloat16 h, l;
        split_val(x, h, l);
        size_t o = (size_t)(c0 + i) * R + r0 + tx;
        oh[o] = h;
        ol[o] = l;
    }
}

// ---------------------------------------------------------------------------
// Fused mask + softmax; reads fp32 S, writes split bf16 P.
// ---------------------------------------------------------------------------
__global__ __launch_bounds__(256) void softmax_mask(
    const float* __restrict__ S, const float* __restrict__ mask,
    __nv_bfloat16* __restrict__ Ph, __nv_bfloat16* __restrict__ Pl)
{
    const int row = blockIdx.x;
    const int b   = row >> 11;
    const int q   = row & (LL - 1);
    const float* mrow = mask + (size_t)b * LL;
    const float mq = (mrow[q] > 0.5f) ? 0.0f : -1.0e9f;
    const float* srow = S + (size_t)row * LL;

    const int t = threadIdx.x;
    float vals[8];
    float lmax = -INFINITY;

#pragma unroll
    for (int v = 0; v < 2; v++) {
        int idx = v * 1024 + t * 4;
        float4 f  = *(const float4*)(srow + idx);
        float4 mk = *(const float4*)(mrow + idx);
        float a;
        a = ((mk.x > 0.5f) ? 0.0f : -1.0e9f) * mq; vals[v * 4 + 0] = f.x + a;
        a = ((mk.y > 0.5f) ? 0.0f : -1.0e9f) * mq; vals[v * 4 + 1] = f.y + a;
        a = ((mk.z > 0.5f) ? 0.0f : -1.0e9f) * mq; vals[v * 4 + 2] = f.z + a;
        a = ((mk.w > 0.5f) ? 0.0f : -1.0e9f) * mq; vals[v * 4 + 3] = f.w + a;
#pragma unroll
        for (int j = 0; j < 4; j++) lmax = fmaxf(lmax, vals[v * 4 + j]);
    }

    __shared__ float red[256];
    red[t] = lmax;
    __syncthreads();
#pragma unroll
    for (int s = 128; s > 0; s >>= 1) {
        if (t < s) red[t] = fmaxf(red[t], red[t + s]);
        __syncthreads();
    }
    const float rmax = red[0];
    __syncthreads();

    float lsum = 0.0f;
#pragma unroll
    for (int i = 0; i < 8; i++) {
        vals[i] = expf(vals[i] - rmax);
        lsum += vals[i];
    }
    red[t] = lsum;
    __syncthreads();
#pragma unroll
    for (int s = 128; s > 0; s >>= 1) {
        if (t < s) red[t] += red[t + s];
        __syncthreads();
    }
    const float inv = 1.0f / red[0];

#pragma unroll
    for (int v = 0; v < 2; v++) {
        int idx = v * 1024 + t * 4;
        float p0 = vals[v * 4 + 0] * inv, p1 = vals[v * 4 + 1] * inv;
        float p2 = vals[v * 4 + 2] * inv, p3 = vals[v * 4 + 3] * inv;
        __nv_bfloat162 h01, l01, h23, l23;
        split_val(p0, h01.x, l01.x); split_val(p1, h01.y, l01.y);
        split_val(p2, h23.x, l23.x); split_val(p3, h23.y, l23.y);
        size_t o = (size_t)row * LL + idx;
        *(__nv_bfloat162*)(Ph + o)     = h01;
        *(__nv_bfloat162*)(Pl + o)     = l01;
        *(__nv_bfloat162*)(Ph + o + 2) = h23;
        *(__nv_bfloat162*)(Pl + o + 2) = l23;
    }
}

// ---------------------------------------------------------------------------
extern "C" void kernel_launch(void* const* d_in, const int* in_sizes, int n_in,
                              void* d_out, int out_size)
{
    const float* in_q  = (const float*)d_in[0];
    const float* in_k  = (const float*)d_in[1];
    const float* kmask = (const float*)d_in[2];
    const float* Wq    = (const float*)d_in[3];
    const float* bq    = (const float*)d_in[4];
    const float* Wk    = (const float*)d_in[5];
    const float* bk    = (const float*)d_in[6];
    float* out = (float*)d_out;

    __nv_bfloat16 *iqh, *iql, *ikh, *ikl, *wqh, *wql, *wkh, *wkl;
    __nv_bfloat16 *Qh, *Ql, *Kh, *Kl, *Vh, *Vl, *Ph, *Pl;
    float* Sp;
    cudaGetSymbolAddress((void**)&iqh, g_iq_h);  cudaGetSymbolAddress((void**)&iql, g_iq_l);
    cudaGetSymbolAddress((void**)&ikh, g_ik_h);  cudaGetSymbolAddress((void**)&ikl, g_ik_l);
    cudaGetSymbolAddress((void**)&wqh, g_Wqt_h); cudaGetSymbolAddress((void**)&wql, g_Wqt_l);
    cudaGetSymbolAddress((void**)&wkh, g_Wkt_h); cudaGetSymbolAddress((void**)&wkl, g_Wkt_l);
    cudaGetSymbolAddress((void**)&Qh,  g_Q_h);   cudaGetSymbolAddress((void**)&Ql,  g_Q_l);
    cudaGetSymbolAddress((void**)&Kh,  g_K_h);   cudaGetSymbolAddress((void**)&Kl,  g_K_l);
    cudaGetSymbolAddress((void**)&Vh,  g_Vt_h);  cudaGetSymbolAddress((void**)&Vl,  g_Vt_l);
    cudaGetSymbolAddress((void**)&Ph,  g_P_h);   cudaGetSymbolAddress((void**)&Pl,  g_P_l);
    cudaGetSymbolAddress((void**)&Sp,  g_S);

    const int SMEM_BYTES = 3 * STAGE_SZ;   // 98304
    cudaFuncSetAttribute(gemm_bf16x3<true, true>,
                         cudaFuncAttributeMaxDynamicSharedMemorySize, SMEM_BYTES);
    cudaFuncSetAttribute(gemm_bf16x3<false, false>,
                         cudaFuncAttributeMaxDynamicSharedMemorySize, SMEM_BYTES);

    // 0) Splits + transposed splits
    split_f32<<<BB * LL * DD / 1024, 256>>>(in_q, iqh, iql);
    split_f32<<<BB * LL * DD / 1024, 256>>>(in_k, ikh, ikl);
    {
        dim3 blk(32, 8);
        transpose_split<<<dim3(HH / 32, DD / 32, 1), blk>>>(Wq, wqh, wql, DD, HH);
        transpose_split<<<dim3(HH / 32, DD / 32, 1), blk>>>(Wk, wkh, wkl, DD, HH);
        transpose_split<<<dim3(DD / 32, LL / 32, BB), blk>>>(in_k, Vh, Vl, LL, DD);
    }

    // 1) Projections (NT, split output)
    {
        dim3 grid(HH / 128, (BB * LL) / 128, 1);
        gemm_bf16x3<true, true><<<grid, 256, SMEM_BYTES>>>(
            iqh, iql, wqh, wql, bq, nullptr, Qh, Ql,
            BB * LL, HH, DD, 1.0f, 0, 0, 0);
        gemm_bf16x3<true, true><<<grid, 256, SMEM_BYTES>>>(
            ikh, ikl, wkh, wkl, bk, nullptr, Kh, Kl,
            BB * LL, HH, DD, 1.0f, 0, 0, 0);
    }

    // 2) Scores: S[b] = (Q[b] @ K[b]^T) / 32
    {
        dim3 grid(LL / 128, LL / 128, BB);
        gemm_bf16x3<false, false><<<grid, 256, SMEM_BYTES>>>(
            Qh, Ql, Kh, Kl, nullptr, Sp, nullptr, nullptr,
            LL, LL, HH, 0.03125f,
            (size_t)LL * HH, (size_t)LL * HH, (size_t)LL * LL);
    }

    // 3) Masked softmax -> split P
    softmax_mask<<<BB * LL, 256>>>(Sp, kmask, Ph, Pl);

    // 4) Output: out[b] = P[b] @ in_k[b]  (NT with Vt)
    {
        dim3 grid(DD / 128, LL / 128, BB);
        gemm_bf16x3<false, false><<<grid, 256, SMEM_BYTES>>>(
            Ph, Pl, Vh, Vl, nullptr, out, nullptr, nullptr,
            LL, DD, LL, 1.0f,
            (size_t)LL * LL, (size_t)DD * LL, (size_t)LL * DD);
    }
}

// round 13
// speedup vs baseline: 1.2612x; 1.0065x over previous
#include <cuda_runtime.h>
#include <cuda_bf16.h>
#include <math.h>
#include <stdint.h>

#define BB 8
#define LL 2048
#define DD 1024
#define HH 1024

// ---------------------------------------------------------------------------
// Scratch (bf16 split pairs + fp32 scores)
// ---------------------------------------------------------------------------
__device__ __nv_bfloat16 g_iq_h[BB * LL * DD], g_iq_l[BB * LL * DD];
__device__ __nv_bfloat16 g_ik_h[BB * LL * DD], g_ik_l[BB * LL * DD];
__device__ __nv_bfloat16 g_Wqt_h[HH * DD], g_Wqt_l[HH * DD];
__device__ __nv_bfloat16 g_Wkt_h[HH * DD], g_Wkt_l[HH * DD];
__device__ __nv_bfloat16 g_Q_h[BB * LL * HH], g_Q_l[BB * LL * HH];
__device__ __nv_bfloat16 g_K_h[BB * LL * HH], g_K_l[BB * LL * HH];
__device__ __nv_bfloat16 g_Vt_h[BB * DD * LL], g_Vt_l[BB * DD * LL];
__device__ __nv_bfloat16 g_P_h[(size_t)BB * LL * LL], g_P_l[(size_t)BB * LL * LL];
__device__ float g_S[(size_t)BB * LL * LL];

// ---------------------------------------------------------------------------
__device__ __forceinline__ uint32_t smem_u32(const void* p) {
    uint32_t a;
    asm("{ .reg .u64 t; cvta.to.shared.u64 t, %1; cvt.u32.u64 %0, t; }" : "=r"(a) : "l"(p));
    return a;
}

#define CP_ASYNC16(dst, src) \
    asm volatile("cp.async.cg.shared.global [%0], [%1], 16;" :: "r"(dst), "l"(src))
#define CP_COMMIT() asm volatile("cp.async.commit_group;" ::: "memory")
#define CP_WAIT(n)  asm volatile("cp.async.wait_group %0;" :: "n"(n) : "memory")

#define LDSM4(R, addr) \
    asm volatile("ldmatrix.sync.aligned.m8n8.x4.shared.b16 {%0,%1,%2,%3}, [%4];" \
        : "=r"((R)[0]), "=r"((R)[1]), "=r"((R)[2]), "=r"((R)[3]) : "r"(addr))

#define MMA16816(D, A, B0, B1) \
    asm volatile("mma.sync.aligned.m16n8k16.row.col.f32.bf16.bf16.f32 " \
        "{%0,%1,%2,%3},{%4,%5,%6,%7},{%8,%9},{%0,%1,%2,%3};" \
        : "+f"((D)[0]), "+f"((D)[1]), "+f"((D)[2]), "+f"((D)[3]) \
        : "r"((A)[0]), "r"((A)[1]), "r"((A)[2]), "r"((A)[3]), "r"(B0), "r"(B1))

__device__ __forceinline__ void split_val(float x, __nv_bfloat16& h, __nv_bfloat16& l) {
    h = __float2bfloat16(x);
    l = __float2bfloat16(x - __bfloat162float(h));
}

// ---------------------------------------------------------------------------
// bf16x3 NT GEMM: C[m,n] = alpha * sum_k A[m,k]*B[n,k] (+bias[n])
// CTA 128x128, BK=32, 3-stage cp.async pipeline (one sync per chunk),
// 8 warps (4m x 2n), warp tile 32x64, XOR-swizzled 64B-stride smem.
// DUAL=true: blockIdx.z selects pointer-set 0/1 (merged projections).
// DUAL=false: blockIdx.z batches via strides sA/sB/sC.
// ---------------------------------------------------------------------------
#define STAGE_SZ 32768
template <bool ADD_BIAS, bool SPLIT_OUT, bool DUAL>
__global__ __launch_bounds__(256, 2) void gemm_bf16x3(
    const __nv_bfloat16* __restrict__ Ah, const __nv_bfloat16* __restrict__ Al,
    const __nv_bfloat16* __restrict__ Bh, const __nv_bfloat16* __restrict__ Bl,
    const float* __restrict__ bias,
    float* __restrict__ Cf, __nv_bfloat16* __restrict__ Ch, __nv_bfloat16* __restrict__ Cl,
    int M, int N, int K, float alpha, size_t sA, size_t sB, size_t sC,
    const __nv_bfloat16* Ah2, const __nv_bfloat16* Al2,
    const __nv_bfloat16* Bh2, const __nv_bfloat16* Bl2,
    const float* bias2, __nv_bfloat16* Ch2, __nv_bfloat16* Cl2)
{
    extern __shared__ char smem[];
    const uint32_t sbase = smem_u32(smem);

    if (DUAL) {
        if (blockIdx.z == 1) {
            Ah = Ah2; Al = Al2; Bh = Bh2; Bl = Bl2;
            bias = bias2; Ch = Ch2; Cl = Cl2;
        }
    } else {
        Ah += (size_t)blockIdx.z * sA;  Al += (size_t)blockIdx.z * sA;
        Bh += (size_t)blockIdx.z * sB;  Bl += (size_t)blockIdx.z * sB;
        if (SPLIT_OUT) { Ch += (size_t)blockIdx.z * sC; Cl += (size_t)blockIdx.z * sC; }
        else           { Cf += (size_t)blockIdx.z * sC; }
    }

    const int t    = threadIdx.x;
    const int lane = t & 31;
    const int wid  = t >> 5;
    const int wm   = wid & 3;          // 4 warps along M (32 rows each)
    const int wn   = wid >> 2;         // 2 warps along N (64 cols each)
    const int rowBase = blockIdx.y * 128;
    const int colBase = blockIdx.x * 128;

    const int nIter = K >> 5;

    // ldmatrix fragment row bases + swizzle selectors
    uint32_t aRow[2], aSw[2], bRow[4], bSw[4];
    const uint32_t cbA = (lane >> 4) & 1;
    const uint32_t cbB = (lane >> 3) & 1;
#pragma unroll
    for (int mt = 0; mt < 2; mt++) {
        uint32_t r = wm * 32 + mt * 16 + (lane & 7) + ((lane >> 3) & 1) * 8;
        aRow[mt] = r * 64;
        aSw[mt]  = (r >> 1) & 3;
    }
#pragma unroll
    for (int np = 0; np < 4; np++) {
        uint32_t r = wn * 64 + np * 16 + (lane & 7) + ((lane >> 4) & 1) * 8;
        bRow[np] = r * 64;
        bSw[np]  = (r >> 1) & 3;
    }

    const int pc = t & 3;

    auto produce = [&](int kt, int stg) {
        const uint32_t s0 = sbase + (uint32_t)stg * STAGE_SZ;
        const int k0 = kt << 5;
#pragma unroll
        for (int i = 0; i < 2; i++) {
            int r = (t >> 2) + i * 64;
            uint32_t sof = (uint32_t)(r * 64 + ((pc ^ ((r >> 1) & 3)) * 16));
            size_t ga = (size_t)(rowBase + r) * K + k0 + pc * 8;
            size_t gb = (size_t)(colBase + r) * K + k0 + pc * 8;
            CP_ASYNC16(s0 + sof,         Ah + ga);
            CP_ASYNC16(s0 + 8192 + sof,  Al + ga);
            CP_ASYNC16(s0 + 16384 + sof, Bh + gb);
            CP_ASYNC16(s0 + 24576 + sof, Bl + gb);
        }
        CP_COMMIT();
    };

    float acc[2][8][4];
#pragma unroll
    for (int i = 0; i < 2; i++)
#pragma unroll
        for (int j = 0; j < 8; j++)
#pragma unroll
            for (int v = 0; v < 4; v++) acc[i][j][v] = 0.0f;

    produce(0, 0);
    produce(1, 1);

    int stage = 0;
    for (int kt = 0; kt < nIter; kt++) {
        if (kt + 1 < nIter) { CP_WAIT(1); } else { CP_WAIT(0); }
        __syncthreads();
        if (kt + 2 < nIter) {
            int ps = stage + 2; if (ps >= 3) ps -= 3;
            produce(kt + 2, ps);
        }

        const uint32_t s0 = sbase + (uint32_t)stage * STAGE_SZ;

#pragma unroll
        for (int ks = 0; ks < 2; ks++) {
            const uint32_t chA = ks * 2 + cbA;
            const uint32_t chB = ks * 2 + cbB;
            uint32_t ah[2][4], al[2][4], bh[8][2];
#pragma unroll
            for (int mt = 0; mt < 2; mt++) {
                uint32_t ad = s0 + aRow[mt] + ((chA ^ aSw[mt]) << 4);
                LDSM4(ah[mt], ad);
                LDSM4(al[mt], ad + 8192);
            }
#pragma unroll
            for (int np = 0; np < 4; np++) {
                uint32_t bd = s0 + 16384 + bRow[np] + ((chB ^ bSw[np]) << 4);
                LDSM4(&bh[2 * np][0], bd);
            }
            // Pass 1: hi*hi
#pragma unroll
            for (int mt = 0; mt < 2; mt++)
#pragma unroll
                for (int nt = 0; nt < 8; nt++)
                    MMA16816(acc[mt][nt], ah[mt], bh[nt][0], bh[nt][1]);
            // Pass 2: lo*hi (al, bh die after this)
#pragma unroll
            for (int mt = 0; mt < 2; mt++)
#pragma unroll
                for (int nt = 0; nt < 8; nt++)
                    MMA16816(acc[mt][nt], al[mt], bh[nt][0], bh[nt][1]);
            // Pass 3: hi*lo (bl reuses dead registers)
            uint32_t bl[8][2];
#pragma unroll
            for (int np = 0; np < 4; np++) {
                uint32_t bd = s0 + 24576 + bRow[np] + ((chB ^ bSw[np]) << 4);
                LDSM4(&bl[2 * np][0], bd);
            }
#pragma unroll
            for (int mt = 0; mt < 2; mt++)
#pragma unroll
                for (int nt = 0; nt < 8; nt++)
                    MMA16816(acc[mt][nt], ah[mt], bl[nt][0], bl[nt][1]);
        }
        stage++; if (stage >= 3) stage = 0;
    }

    // Epilogue
#pragma unroll
    for (int mt = 0; mt < 2; mt++) {
#pragma unroll
        for (int nt = 0; nt < 8; nt++) {
            int row = rowBase + wm * 32 + mt * 16 + (lane >> 2);
            int col = colBase + wn * 64 + nt * 8 + 2 * (lane & 3);
            float v0 = acc[mt][nt][0] * alpha;
            float v1 = acc[mt][nt][1] * alpha;
            float v2 = acc[mt][nt][2] * alpha;
            float v3 = acc[mt][nt][3] * alpha;
            if (ADD_BIAS) {
                float b0 = bias[col], b1 = bias[col + 1];
                v0 += b0; v1 += b1; v2 += b0; v3 += b1;
            }
            if (SPLIT_OUT) {
                __nv_bfloat162 h01, l01, h23, l23;
                split_val(v0, h01.x, l01.x); split_val(v1, h01.y, l01.y);
                split_val(v2, h23.x, l23.x); split_val(v3, h23.y, l23.y);
                *(__nv_bfloat162*)(Ch + (size_t)row * N + col)       = h01;
                *(__nv_bfloat162*)(Cl + (size_t)row * N + col)       = l01;
                *(__nv_bfloat162*)(Ch + (size_t)(row + 8) * N + col) = h23;
                *(__nv_bfloat162*)(Cl + (size_t)(row + 8) * N + col) = l23;
            } else {
                *(float2*)(Cf + (size_t)row * N + col)       = make_float2(v0, v1);
                *(float2*)(Cf + (size_t)(row + 8) * N + col) = make_float2(v2, v3);
            }
        }
    }
}

// ---------------------------------------------------------------------------
// Merged elementwise split for both inputs: one launch covers in_q and in_k.
// ---------------------------------------------------------------------------
__global__ __launch_bounds__(256) void split_f32_dual(
    const float* __restrict__ inA, __nv_bfloat16* __restrict__ hA,
    __nv_bfloat16* __restrict__ lA,
    const float* __restrict__ inB, __nv_bfloat16* __restrict__ hB,
    __nv_bfloat16* __restrict__ lB, int halfBlocks)
{
    const float* in; __nv_bfloat16 *h, *l;
    int bx = blockIdx.x;
    if (bx < halfBlocks) { in = inA; h = hA; l = lA; }
    else                 { in = inB; h = hB; l = lB; bx -= halfBlocks; }
    size_t i = ((size_t)bx * 256 + threadIdx.x) * 4;
    float4 v = *(const float4*)(in + i);
    __nv_bfloat162 h01, l01, h23, l23;
    split_val(v.x, h01.x, l01.x); split_val(v.y, h01.y, l01.y);
    split_val(v.z, h23.x, l23.x); split_val(v.w, h23.y, l23.y);
    *(__nv_bfloat162*)(h + i)     = h01;
    *(__nv_bfloat162*)(l + i)     = l01;
    *(__nv_bfloat162*)(h + i + 2) = h23;
    *(__nv_bfloat162*)(l + i + 2) = l23;
}

// ---------------------------------------------------------------------------
// Transpose + split: out_{h,l}[c][r] = split(in[r][c]); batched over z.
// ---------------------------------------------------------------------------
__global__ __launch_bounds__(256) void transpose_split(
    const float* __restrict__ in, __nv_bfloat16* __restrict__ oh,
    __nv_bfloat16* __restrict__ ol, int R, int C)
{
    __shared__ float tile[32][33];
    in += (size_t)blockIdx.z * R * C;
    oh += (size_t)blockIdx.z * R * C;
    ol += (size_t)blockIdx.z * R * C;
    const int r0 = blockIdx.y * 32, c0 = blockIdx.x * 32;
    const int tx = threadIdx.x, ty = threadIdx.y;
#pragma unroll
    for (int i = ty; i < 32; i += 8)
        tile[i][tx] = in[(size_t)(r0 + i) * C + c0 + tx];
    __syncthreads();
#pragma unroll
    for (int i = ty; i < 32; i += 8) {
        float x = tile[tx][i];
        __nv_bfloat16 h, l;
        split_val(x, h, l);
        size_t o = (size_t)(c0 + i) * R + r0 + tx;
        oh[o] = h;
        ol[o] = l;
    }
}

// ---------------------------------------------------------------------------
// Fused mask + softmax; 512 threads, warp-shuffle reductions (2 barriers).
// Reads fp32 S, writes split bf16 P.
// ---------------------------------------------------------------------------
__global__ __launch_bounds__(512) void softmax_mask(
    const float* __restrict__ S, const float* __restrict__ mask,
    __nv_bfloat16* __restrict__ Ph, __nv_bfloat16* __restrict__ Pl)
{
    const int row = blockIdx.x;
    const int b   = row >> 11;
    const int q   = row & (LL - 1);
    const float* mrow = mask + (size_t)b * LL;
    const float mq = (mrow[q] > 0.5f) ? 0.0f : -1.0e9f;
    const float* srow = S + (size_t)row * LL;

    const int t    = threadIdx.x;
    const int lane = t & 31;
    const int wrp  = t >> 5;
    const int idx  = t * 4;

    float4 f  = *(const float4*)(srow + idx);
    float4 mk = *(const float4*)(mrow + idx);
    float vals[4];
    {
        float a;
        a = ((mk.x > 0.5f) ? 0.0f : -1.0e9f) * mq; vals[0] = f.x + a;
        a = ((mk.y > 0.5f) ? 0.0f : -1.0e9f) * mq; vals[1] = f.y + a;
        a = ((mk.z > 0.5f) ? 0.0f : -1.0e9f) * mq; vals[2] = f.z + a;
        a = ((mk.w > 0.5f) ? 0.0f : -1.0e9f) * mq; vals[3] = f.w + a;
    }
    float lmax = fmaxf(fmaxf(vals[0], vals[1]), fmaxf(vals[2], vals[3]));
#pragma unroll
    for (int o = 16; o > 0; o >>= 1)
        lmax = fmaxf(lmax, __shfl_xor_sync(0xFFFFFFFFu, lmax, o));

    __shared__ float red[16];
    if (lane == 0) red[wrp] = lmax;
    __syncthreads();
    float rmax = red[0];
#pragma unroll
    for (int i = 1; i < 16; i++) rmax = fmaxf(rmax, red[i]);

    float lsum = 0.0f;
#pragma unroll
    for (int i = 0; i < 4; i++) {
        vals[i] = expf(vals[i] - rmax);
        lsum += vals[i];
    }
#pragma unroll
    for (int o = 16; o > 0; o >>= 1)
        lsum += __shfl_xor_sync(0xFFFFFFFFu, lsum, o);

    __shared__ float red2[16];
    if (lane == 0) red2[wrp] = lsum;
    __syncthreads();
    float rsum = 0.0f;
#pragma unroll
    for (int i = 0; i < 16; i++) rsum += red2[i];
    const float inv = 1.0f / rsum;

    float p0 = vals[0] * inv, p1 = vals[1] * inv;
    float p2 = vals[2] * inv, p3 = vals[3] * inv;
    __nv_bfloat162 h01, l01, h23, l23;
    split_val(p0, h01.x, l01.x); split_val(p1, h01.y, l01.y);
    split_val(p2, h23.x, l23.x); split_val(p3, h23.y, l23.y);
    size_t o = (size_t)row * LL + idx;
    *(__nv_bfloat162*)(Ph + o)     = h01;
    *(__nv_bfloat162*)(Pl + o)     = l01;
    *(__nv_bfloat162*)(Ph + o + 2) = h23;
    *(__nv_bfloat162*)(Pl + o + 2) = l23;
}

// ---------------------------------------------------------------------------
extern "C" void kernel_launch(void* const* d_in, const int* in_sizes, int n_in,
                              void* d_out, int out_size)
{
    const float* in_q  = (const float*)d_in[0];
    const float* in_k  = (const float*)d_in[1];
    const float* kmask = (const float*)d_in[2];
    const float* Wq    = (const float*)d_in[3];
    const float* bq    = (const float*)d_in[4];
    const float* Wk    = (const float*)d_in[5];
    const float* bk    = (const float*)d_in[6];
    float* out = (float*)d_out;

    __nv_bfloat16 *iqh, *iql, *ikh, *ikl, *wqh, *wql, *wkh, *wkl;
    __nv_bfloat16 *Qh, *Ql, *Kh, *Kl, *Vh, *Vl, *Ph, *Pl;
    float* Sp;
    cudaGetSymbolAddress((void**)&iqh, g_iq_h);  cudaGetSymbolAddress((void**)&iql, g_iq_l);
    cudaGetSymbolAddress((void**)&ikh, g_ik_h);  cudaGetSymbolAddress((void**)&ikl, g_ik_l);
    cudaGetSymbolAddress((void**)&wqh, g_Wqt_h); cudaGetSymbolAddress((void**)&wql, g_Wqt_l);
    cudaGetSymbolAddress((void**)&wkh, g_Wkt_h); cudaGetSymbolAddress((void**)&wkl, g_Wkt_l);
    cudaGetSymbolAddress((void**)&Qh,  g_Q_h);   cudaGetSymbolAddress((void**)&Ql,  g_Q_l);
    cudaGetSymbolAddress((void**)&Kh,  g_K_h);   cudaGetSymbolAddress((void**)&Kl,  g_K_l);
    cudaGetSymbolAddress((void**)&Vh,  g_Vt_h);  cudaGetSymbolAddress((void**)&Vl,  g_Vt_l);
    cudaGetSymbolAddress((void**)&Ph,  g_P_h);   cudaGetSymbolAddress((void**)&Pl,  g_P_l);
    cudaGetSymbolAddress((void**)&Sp,  g_S);

    const int SMEM_BYTES = 3 * STAGE_SZ;   // 98304
    cudaFuncSetAttribute(gemm_bf16x3<true, true, true>,
                         cudaFuncAttributeMaxDynamicSharedMemorySize, SMEM_BYTES);
    cudaFuncSetAttribute(gemm_bf16x3<false, false, false>,
                         cudaFuncAttributeMaxDynamicSharedMemorySize, SMEM_BYTES);

    // 0) Splits + transposed splits
    {
        int half = BB * LL * DD / 1024;
        split_f32_dual<<<2 * half, 256>>>(in_q, iqh, iql, in_k, ikh, ikl, half);
        dim3 blk(32, 8);
        transpose_split<<<dim3(HH / 32, DD / 32, 1), blk>>>(Wq, wqh, wql, DD, HH);
        transpose_split<<<dim3(HH / 32, DD / 32, 1), blk>>>(Wk, wkh, wkl, DD, HH);
        transpose_split<<<dim3(DD / 32, LL / 32, BB), blk>>>(in_k, Vh, Vl, LL, DD);
    }

    // 1) Both projections in ONE launch (z=0: Q-set, z=1: K-set)
    {
        dim3 grid(HH / 128, (BB * LL) / 128, 2);
        gemm_bf16x3<true, true, true><<<grid, 256, SMEM_BYTES>>>(
            iqh, iql, wqh, wql, bq, nullptr, Qh, Ql,
            BB * LL, HH, DD, 1.0f, 0, 0, 0,
            ikh, ikl, wkh, wkl, bk, Kh, Kl);
    }

    // 2) Scores: S[b] = (Q[b] @ K[b]^T) / 32
    {
        dim3 grid(LL / 128, LL / 128, BB);
        gemm_bf16x3<false, false, false><<<grid, 256, SMEM_BYTES>>>(
            Qh, Ql, Kh, Kl, nullptr, Sp, nullptr, nullptr,
            LL, LL, HH, 0.03125f,
            (size_t)LL * HH, (size_t)LL * HH, (size_t)LL * LL,
            nullptr, nullptr, nullptr, nullptr, nullptr, nullptr, nullptr);
    }

    // 3) Masked softmax -> split P
    softmax_mask<<<BB * LL, 512>>>(Sp, kmask, Ph, Pl);

    // 4) Output: out[b] = P[b] @ in_k[b]  (NT with Vt)
    {
        dim3 grid(DD / 128, LL / 128, BB);
        gemm_bf16x3<false, false, false><<<grid, 256, SMEM_BYTES>>>(
            Ph, Pl, Vh, Vl, nullptr, out, nullptr, nullptr,
            LL, DD, LL, 1.0f,
            (size_t)LL * LL, (size_t)DD * LL, (size_t)LL * DD,
            nullptr, nullptr, nullptr, nullptr, nullptr, nullptr, nullptr);
    }
}